// round 10
// baseline (speedup 1.0000x reference)
#include <cuda_runtime.h>
#include <cuda_bf16.h>
#include <cstdint>
#include <cstddef>

// Problem constants (fixed by reference)
#define NNODES 30000
#define EMAX   600000
#define WIDTH  256      // heads(4) * per-head(64)
#define QKVS_W 1024     // q|k|v|s concatenated

// ================= scratch (static device globals; no allocation) ===========
__device__ __align__(16) float g_qkvs [(size_t)NNODES * QKVS_W];
__device__ __align__(16) float g_accum[(size_t)NNODES * WIDTH];
__device__ __align__(16) float g_stats[2 * WIDTH];          // sum | sumsq
__device__ int g_is64;

// CSR scratch (built once per launch; reused by both layers)
__device__ int g_deg[NNODES];
__device__ int g_off[NNODES + 1];
__device__ int g_pos[NNODES];
__device__ int g_csr[EMAX];

// bf16 split-precision scratch
__device__ __align__(16) __nv_bfloat16 g_ahi [(size_t)NNODES * 256];
__device__ __align__(16) __nv_bfloat16 g_alo [(size_t)NNODES * 256];
__device__ __align__(16) __nv_bfloat16 g_bthi[2u * 1024 * 256];   // Bt[n][k] per layer
__device__ __align__(16) __nv_bfloat16 g_btlo[2u * 1024 * 256];
__device__ __align__(16) float         g_biasc[2 * 1024];

// ================= small kernels =============================================
__global__ void __launch_bounds__(512) detect_idx_kernel(
    const int* __restrict__ ei32, int nwords) {
    __shared__ int bad;
    if (threadIdx.x == 0) bad = 0;
    __syncthreads();
    int lim = nwords < 4096 ? nwords : 4096;
    int nz = 0;
    for (int i = 1 + 2 * threadIdx.x; i < lim; i += 2 * 512)
        nz |= (ei32[i] != 0);
    if (nz) atomicOr(&bad, 1);
    __syncthreads();
    if (threadIdx.x == 0) g_is64 = !bad;
}

__device__ __forceinline__ int load_idx(const void* ei, int i) {
    if (g_is64) return (int)((const long long*)ei)[i];
    return ((const int*)ei)[i];
}

__global__ void hist_kernel(const void* __restrict__ ei, int* __restrict__ deg,
                            int E, int M) {
    int e = blockIdx.x * blockDim.x + threadIdx.x;
    if (e >= E) return;
    int dst = load_idx(ei, E + e);
    if ((unsigned)dst < (unsigned)M) atomicAdd(&deg[dst], 1);
}

__global__ void __launch_bounds__(1024) scan_kernel(
    const int* __restrict__ deg, int* __restrict__ off, int* __restrict__ pos, int n) {
    __shared__ int s[1024];
    int t = threadIdx.x;
    int chunk = (n + 1023) / 1024;
    int base = t * chunk;
    int sum = 0;
    for (int i = 0; i < chunk; i++) {
        int idx = base + i;
        if (idx < n) sum += deg[idx];
    }
    s[t] = sum;
    __syncthreads();
    for (int d = 1; d < 1024; d <<= 1) {
        int u = (t >= d) ? s[t - d] : 0;
        __syncthreads();
        s[t] += u;
        __syncthreads();
    }
    int run = s[t] - sum;
    for (int i = 0; i < chunk; i++) {
        int idx = base + i;
        if (idx < n) {
            off[idx] = run;
            pos[idx] = run;
            run += deg[idx];
        }
    }
    if (t == 1023) off[n] = s[1023];
}

__global__ void scatter_kernel(const void* __restrict__ ei, int* __restrict__ pos,
                               int* __restrict__ csr, int E, int M) {
    int e = blockIdx.x * blockDim.x + threadIdx.x;
    if (e >= E) return;
    int src = load_idx(ei, e);
    int dst = load_idx(ei, E + e);
    if ((unsigned)dst >= (unsigned)M || (unsigned)src >= (unsigned)M) return;
    int p = atomicAdd(&pos[dst], 1);
    csr[p] = src;
}

// split fp32 -> bf16 hi/lo (4 elems/thread)
__global__ void split_a_kernel(const float* __restrict__ src,
                               __nv_bfloat16* __restrict__ hi,
                               __nv_bfloat16* __restrict__ lo, int n4) {
    int i = blockIdx.x * blockDim.x + threadIdx.x;
    int s = gridDim.x * blockDim.x;
    for (; i < n4; i += s) {
        float4 v = ((const float4*)src)[i];
        __nv_bfloat16 h0 = __float2bfloat16(v.x), h1 = __float2bfloat16(v.y);
        __nv_bfloat16 h2 = __float2bfloat16(v.z), h3 = __float2bfloat16(v.w);
        __nv_bfloat16 l0 = __float2bfloat16(v.x - __bfloat162float(h0));
        __nv_bfloat16 l1 = __float2bfloat16(v.y - __bfloat162float(h1));
        __nv_bfloat16 l2 = __float2bfloat16(v.z - __bfloat162float(h2));
        __nv_bfloat16 l3 = __float2bfloat16(v.w - __bfloat162float(h3));
        ((__nv_bfloat162*)hi)[i * 2]     = __nv_bfloat162(h0, h1);
        ((__nv_bfloat162*)hi)[i * 2 + 1] = __nv_bfloat162(h2, h3);
        ((__nv_bfloat162*)lo)[i * 2]     = __nv_bfloat162(l0, l1);
        ((__nv_bfloat162*)lo)[i * 2 + 1] = __nv_bfloat162(l2, l3);
    }
}

struct WPtrs { const float* w[8]; const float* b[8]; };

__global__ void prep_weights(WPtrs P, __nv_bfloat16* __restrict__ bthi,
                             __nv_bfloat16* __restrict__ btlo) {
    const float* W = P.w[blockIdx.z];
    int layer = blockIdx.z >> 2, j = blockIdx.z & 3;
    __shared__ float t[32][33];
    int tx = threadIdx.x, ty = threadIdx.y;
    int c0 = blockIdx.x * 32, k0 = blockIdx.y * 32;
#pragma unroll
    for (int r = 0; r < 4; r++) {
        int k = k0 + ty + r * 8;
        t[ty + r * 8][tx] = W[k * 256 + c0 + tx];
    }
    __syncthreads();
#pragma unroll
    for (int r = 0; r < 4; r++) {
        int c = c0 + ty + r * 8;
        int k = k0 + tx;
        float v = t[tx][ty + r * 8];
        __nv_bfloat16 h = __float2bfloat16(v);
        size_t o = ((size_t)layer * 1024 + j * 256 + c) * 256 + k;
        bthi[o] = h;
        btlo[o] = __float2bfloat16(v - __bfloat162float(h));
    }
}

__global__ void prep_bias(WPtrs P, float* __restrict__ biasc) {
    int idx = blockIdx.x * blockDim.x + threadIdx.x;
    if (idx < 2048) {
        int layer = idx >> 10, j = (idx >> 8) & 3, c = idx & 255;
        biasc[idx] = P.b[layer * 4 + j][c];
    }
}

// ================= mma.sync bf16 GEMM, 2-stage cp.async pipeline =============
#define KPAD 72
#define TILE_B (128 * KPAD)         // bf16 elems per tile
#define STAGE_B (4 * TILE_B)        // 4 tiles (Ah,Al,Bh,Bl) per stage
#define SM_BYTES (2 * STAGE_B * 2)  // 147456 bytes

__device__ __forceinline__ void mma16816(float* d, const uint32_t* a,
                                          const uint32_t* b) {
    asm volatile(
        "mma.sync.aligned.m16n8k16.row.col.f32.bf16.bf16.f32 "
        "{%0,%1,%2,%3}, {%4,%5,%6,%7}, {%8,%9}, {%0,%1,%2,%3};"
        : "+f"(d[0]), "+f"(d[1]), "+f"(d[2]), "+f"(d[3])
        : "r"(a[0]), "r"(a[1]), "r"(a[2]), "r"(a[3]), "r"(b[0]), "r"(b[1]));
}

__device__ __forceinline__ void cpa16(uint32_t dst_s, const void* src, bool valid) {
    int sz = valid ? 16 : 0;
    asm volatile("cp.async.cg.shared.global [%0], [%1], 16, %2;"
                 :: "r"(dst_s), "l"(src), "r"(sz));
}

__device__ __forceinline__ void load_tile_async(
    uint32_t s, const __nv_bfloat16* __restrict__ g,
    int row0, int rowlim, int k0, int tid) {
#pragma unroll
    for (int it = 0; it < 4; it++) {
        int idx = it * 256 + tid;
        int row = idx >> 3;
        int c8  = (idx & 7) * 8;
        int r = row0 + row;
        cpa16(s + (row * KPAD + c8) * 2, g + (size_t)r * 256 + k0 + c8, r < rowlim);
    }
}

__device__ __forceinline__ void issue_stage(
    uint32_t sb, int stage,
    const __nv_bfloat16* ahi, const __nv_bfloat16* alo,
    const __nv_bfloat16* bh, const __nv_bfloat16* bl,
    int m0, int M, int k0, int tid) {
    uint32_t s = sb + stage * STAGE_B * 2;
    load_tile_async(s,                ahi, m0, M, k0, tid);
    load_tile_async(s + TILE_B * 2,   alo, m0, M, k0, tid);
    load_tile_async(s + TILE_B * 4,   bh, 0, 1 << 30, k0, tid);
    load_tile_async(s + TILE_B * 6,   bl, 0, 1 << 30, k0, tid);
    asm volatile("cp.async.commit_group;");
}

__global__ void __launch_bounds__(256) gemm_mma(
    const __nv_bfloat16* __restrict__ ahi, const __nv_bfloat16* __restrict__ alo,
    const __nv_bfloat16* __restrict__ bthi, const __nv_bfloat16* __restrict__ btlo,
    const float* __restrict__ bias, float* __restrict__ out, int M)
{
    extern __shared__ __align__(16) __nv_bfloat16 sm[];
    uint32_t sb = (uint32_t)__cvta_generic_to_shared(sm);

    const int tid = threadIdx.x;
    const int wid = tid >> 5, lane = tid & 31;
    const int wm = wid & 3, wn = wid >> 2;
    const int g = lane >> 2, t = lane & 3;
    const int nt = blockIdx.x;
    const int m0 = blockIdx.y * 128;

    const __nv_bfloat16* bh = bthi + (size_t)nt * 128 * 256;
    const __nv_bfloat16* bl = btlo + (size_t)nt * 128 * 256;

    float acc[2][8][4];
#pragma unroll
    for (int i = 0; i < 2; i++)
#pragma unroll
        for (int j = 0; j < 8; j++)
#pragma unroll
            for (int k = 0; k < 4; k++) acc[i][j][k] = 0.f;

    issue_stage(sb, 0, ahi, alo, bh, bl, m0, M, 0, tid);

    for (int kc = 0; kc < 4; kc++) {
        if (kc + 1 < 4) {
            issue_stage(sb, (kc + 1) & 1, ahi, alo, bh, bl, m0, M, (kc + 1) * 64, tid);
            asm volatile("cp.async.wait_group 1;");
        } else {
            asm volatile("cp.async.wait_group 0;");
        }
        __syncthreads();

        const __nv_bfloat16* sAh = sm + (kc & 1) * STAGE_B;
        const __nv_bfloat16* sAl = sAh + TILE_B;
        const __nv_bfloat16* sBh = sAh + 2 * TILE_B;
        const __nv_bfloat16* sBl = sAh + 3 * TILE_B;

#pragma unroll
        for (int ks = 0; ks < 4; ks++) {
            const int kb = ks * 16 + t * 2;
            uint32_t a_h[2][4], a_l[2][4];
#pragma unroll
            for (int mf = 0; mf < 2; mf++) {
                int r = wm * 32 + mf * 16 + g;
                a_h[mf][0] = *(const uint32_t*)(sAh + r * KPAD + kb);
                a_h[mf][1] = *(const uint32_t*)(sAh + (r + 8) * KPAD + kb);
                a_h[mf][2] = *(const uint32_t*)(sAh + r * KPAD + kb + 8);
                a_h[mf][3] = *(const uint32_t*)(sAh + (r + 8) * KPAD + kb + 8);
                a_l[mf][0] = *(const uint32_t*)(sAl + r * KPAD + kb);
                a_l[mf][1] = *(const uint32_t*)(sAl + (r + 8) * KPAD + kb);
                a_l[mf][2] = *(const uint32_t*)(sAl + r * KPAD + kb + 8);
                a_l[mf][3] = *(const uint32_t*)(sAl + (r + 8) * KPAD + kb + 8);
            }
#pragma unroll
            for (int nf = 0; nf < 8; nf++) {
                int c = wn * 64 + nf * 8 + g;
                uint32_t b_h[2], b_l[2];
                b_h[0] = *(const uint32_t*)(sBh + c * KPAD + kb);
                b_h[1] = *(const uint32_t*)(sBh + c * KPAD + kb + 8);
                b_l[0] = *(const uint32_t*)(sBl + c * KPAD + kb);
                b_l[1] = *(const uint32_t*)(sBl + c * KPAD + kb + 8);
#pragma unroll
                for (int mf = 0; mf < 2; mf++) {
                    mma16816(acc[mf][nf], a_h[mf], b_h);
                    mma16816(acc[mf][nf], a_h[mf], b_l);
                    mma16816(acc[mf][nf], a_l[mf], b_h);
                }
            }
        }
        __syncthreads();
    }

#pragma unroll
    for (int mf = 0; mf < 2; mf++) {
        int r0 = m0 + wm * 32 + mf * 16 + g;
#pragma unroll
        for (int nf = 0; nf < 8; nf++) {
            int cg = nt * 128 + wn * 64 + nf * 8 + t * 2;
            float bx = bias[cg], by = bias[cg + 1];
            if (r0 < M) {
                float2 o = make_float2(acc[mf][nf][0] + bx, acc[mf][nf][1] + by);
                *(float2*)(out + (size_t)r0 * QKVS_W + cg) = o;
            }
            if (r0 + 8 < M) {
                float2 o = make_float2(acc[mf][nf][2] + bx, acc[mf][nf][3] + by);
                *(float2*)(out + (size_t)(r0 + 8) * QKVS_W + cg) = o;
            }
        }
    }
}

// ===== gather edge aggregation (2-edge unroll) + fused BN statistics ========
__global__ void __launch_bounds__(256) edge_agg(
    const float* __restrict__ qkvs,
    const int* __restrict__ off, const int* __restrict__ csr,
    float* __restrict__ accum, float* __restrict__ stats, int M)
{
    __shared__ float ssum[WIDTH];
    __shared__ float ssq[WIDTH];
    const int tid = threadIdx.x;
    ssum[tid] = 0.f;
    ssq[tid] = 0.f;
    __syncthreads();

    int warp = (blockIdx.x * blockDim.x + tid) >> 5;
    int lane = tid & 31;

    if (warp < M) {
        const float4* qp = (const float4*)(qkvs + (size_t)warp * QKVS_W);
        float4 q0 = __ldg(&qp[lane * 2]), q1 = __ldg(&qp[lane * 2 + 1]);

        int i0 = off[warp], i1 = off[warp + 1];
        float a0x = 0.f, a0y = 0.f, a0z = 0.f, a0w = 0.f;
        float a1x = 0.f, a1y = 0.f, a1z = 0.f, a1w = 0.f;
        float dsum = 0.f;

        int i = i0;
        for (; i + 2 <= i1; i += 2) {
            int sa = __ldg(&csr[i]), sb = __ldg(&csr[i + 1]);
            const float4* kpa = (const float4*)(qkvs + (size_t)sa * QKVS_W + 256);
            const float4* vpa = (const float4*)(qkvs + (size_t)sa * QKVS_W + 512);
            const float4* kpb = (const float4*)(qkvs + (size_t)sb * QKVS_W + 256);
            const float4* vpb = (const float4*)(qkvs + (size_t)sb * QKVS_W + 512);
            float4 ka0 = __ldg(&kpa[lane * 2]), ka1 = __ldg(&kpa[lane * 2 + 1]);
            float4 kb0 = __ldg(&kpb[lane * 2]), kb1 = __ldg(&kpb[lane * 2 + 1]);
            float4 va0 = __ldg(&vpa[lane * 2]), va1 = __ldg(&vpa[lane * 2 + 1]);
            float4 vb0 = __ldg(&vpb[lane * 2]), vb1 = __ldg(&vpb[lane * 2 + 1]);

            float pa = q0.x * ka0.x + q0.y * ka0.y + q0.z * ka0.z + q0.w * ka0.w
                     + q1.x * ka1.x + q1.y * ka1.y + q1.z * ka1.z + q1.w * ka1.w;
            float pb = q0.x * kb0.x + q0.y * kb0.y + q0.z * kb0.z + q0.w * kb0.w
                     + q1.x * kb1.x + q1.y * kb1.y + q1.z * kb1.z + q1.w * kb1.w;
            pa += __shfl_xor_sync(0xffffffffu, pa, 1);
            pb += __shfl_xor_sync(0xffffffffu, pb, 1);
            pa += __shfl_xor_sync(0xffffffffu, pa, 2);
            pb += __shfl_xor_sync(0xffffffffu, pb, 2);
            pa += __shfl_xor_sync(0xffffffffu, pa, 4);
            pb += __shfl_xor_sync(0xffffffffu, pb, 4);
            float exa = __expf(pa * 0.125f);
            float exb = __expf(pb * 0.125f);
            dsum += exa + exb;
            a0x += va0.x * exa + vb0.x * exb; a0y += va0.y * exa + vb0.y * exb;
            a0z += va0.z * exa + vb0.z * exb; a0w += va0.w * exa + vb0.w * exb;
            a1x += va1.x * exa + vb1.x * exb; a1y += va1.y * exa + vb1.y * exb;
            a1z += va1.z * exa + vb1.z * exb; a1w += va1.w * exa + vb1.w * exb;
        }
        if (i < i1) {
            int s = __ldg(&csr[i]);
            const float4* kp = (const float4*)(qkvs + (size_t)s * QKVS_W + 256);
            const float4* vp = (const float4*)(qkvs + (size_t)s * QKVS_W + 512);
            float4 k0 = __ldg(&kp[lane * 2]), k1 = __ldg(&kp[lane * 2 + 1]);
            float4 v0 = __ldg(&vp[lane * 2]), v1 = __ldg(&vp[lane * 2 + 1]);
            float p = q0.x * k0.x + q0.y * k0.y + q0.z * k0.z + q0.w * k0.w
                    + q1.x * k1.x + q1.y * k1.y + q1.z * k1.z + q1.w * k1.w;
            p += __shfl_xor_sync(0xffffffffu, p, 1);
            p += __shfl_xor_sync(0xffffffffu, p, 2);
            p += __shfl_xor_sync(0xffffffffu, p, 4);
            float ex = __expf(p * 0.125f);
            dsum += ex;
            a0x += v0.x * ex; a0y += v0.y * ex; a0z += v0.z * ex; a0w += v0.w * ex;
            a1x += v1.x * ex; a1y += v1.y * ex; a1z += v1.z * ex; a1w += v1.w * ex;
        }

        float inv = (dsum > 0.f) ? (1.0f / dsum) : 0.f;
        const float4* sp = (const float4*)(qkvs + (size_t)warp * QKVS_W + 768);
        float4 s0 = __ldg(&sp[lane * 2]), s1 = __ldg(&sp[lane * 2 + 1]);
        float4 o0 = make_float4(a0x * inv + s0.x, a0y * inv + s0.y,
                                a0z * inv + s0.z, a0w * inv + s0.w);
        float4 o1 = make_float4(a1x * inv + s1.x, a1y * inv + s1.y,
                                a1z * inv + s1.z, a1w * inv + s1.w);
        float4* op = (float4*)(accum + (size_t)warp * WIDTH + lane * 8);
        op[0] = o0;
        op[1] = o1;

        // fused BN stats: per-CTA smem reduce (disjoint addrs within a warp)
        int cb = lane * 8;
        atomicAdd(&ssum[cb + 0], o0.x); atomicAdd(&ssq[cb + 0], o0.x * o0.x);
        atomicAdd(&ssum[cb + 1], o0.y); atomicAdd(&ssq[cb + 1], o0.y * o0.y);
        atomicAdd(&ssum[cb + 2], o0.z); atomicAdd(&ssq[cb + 2], o0.z * o0.z);
        atomicAdd(&ssum[cb + 3], o0.w); atomicAdd(&ssq[cb + 3], o0.w * o0.w);
        atomicAdd(&ssum[cb + 4], o1.x); atomicAdd(&ssq[cb + 4], o1.x * o1.x);
        atomicAdd(&ssum[cb + 5], o1.y); atomicAdd(&ssq[cb + 5], o1.y * o1.y);
        atomicAdd(&ssum[cb + 6], o1.z); atomicAdd(&ssq[cb + 6], o1.z * o1.z);
        atomicAdd(&ssum[cb + 7], o1.w); atomicAdd(&ssq[cb + 7], o1.w * o1.w);
    }
    __syncthreads();
    atomicAdd(&stats[tid], ssum[tid]);
    atomicAdd(&stats[WIDTH + tid], ssq[tid]);
}

// ================= BN apply ==================================================
__global__ void __launch_bounds__(256) bn_act(
    const float* __restrict__ in, const float* __restrict__ stats,
    const float* __restrict__ gamma, const float* __restrict__ beta,
    float* __restrict__ out, int M, float invN)
{
    int idx = blockIdx.x * blockDim.x + threadIdx.x;
    int total = M * WIDTH;
    int stride = gridDim.x * blockDim.x;
    for (; idx < total; idx += stride) {
        int c = idx & (WIDTH - 1);
        float mean = stats[c] * invN;
        float var  = stats[WIDTH + c] * invN - mean * mean;
        float sc = rsqrtf(var + 1e-5f) * gamma[c];
        float sh = beta[c] - mean * sc;
        float v = in[idx] * sc + sh;
        out[idx] = (v >= 0.f) ? v : 0.1f * v;
    }
}

// BN + leaky-relu + bf16 hi/lo split, feeding the next GEMM directly
__global__ void __launch_bounds__(256) bn_act_split(
    const float* __restrict__ in, const float* __restrict__ stats,
    const float* __restrict__ gamma, const float* __restrict__ beta,
    __nv_bfloat16* __restrict__ hi, __nv_bfloat16* __restrict__ lo,
    int n4, float invN)
{
    int i = blockIdx.x * blockDim.x + threadIdx.x;
    int stride = gridDim.x * blockDim.x;
    for (; i < n4; i += stride) {
        int c = (i & 63) * 4;
        float4 v = ((const float4*)in)[i];
        float r[4] = {v.x, v.y, v.z, v.w};
        __nv_bfloat16 hh[4], ll[4];
#pragma unroll
        for (int j = 0; j < 4; j++) {
            int cc = c + j;
            float mean = stats[cc] * invN;
            float var  = stats[WIDTH + cc] * invN - mean * mean;
            float sc = rsqrtf(var + 1e-5f) * gamma[cc];
            float sh = beta[cc] - mean * sc;
            float x = r[j] * sc + sh;
            x = (x >= 0.f) ? x : 0.1f * x;
            hh[j] = __float2bfloat16(x);
            ll[j] = __float2bfloat16(x - __bfloat162float(hh[j]));
        }
        ((__nv_bfloat162*)hi)[i * 2]     = __nv_bfloat162(hh[0], hh[1]);
        ((__nv_bfloat162*)hi)[i * 2 + 1] = __nv_bfloat162(hh[2], hh[3]);
        ((__nv_bfloat162*)lo)[i * 2]     = __nv_bfloat162(ll[0], ll[1]);
        ((__nv_bfloat162*)lo)[i * 2 + 1] = __nv_bfloat162(ll[2], ll[3]);
    }
}

// ================= launch ====================================================
extern "C" void kernel_launch(void* const* d_in, const int* in_sizes, int n_in,
                              void* d_out, int out_size)
{
    const float* x  = (const float*)d_in[0];
    const void*  ei = d_in[1];
    WPtrs wp;
    for (int i = 0; i < 4; i++) {
        wp.w[i]     = (const float*)d_in[2 + i * 2];
        wp.b[i]     = (const float*)d_in[3 + i * 2];
        wp.w[4 + i] = (const float*)d_in[12 + i * 2];
        wp.b[4 + i] = (const float*)d_in[13 + i * 2];
    }
    const float* g1  = (const float*)d_in[10]; const float* be1 = (const float*)d_in[11];
    const float* g2  = (const float*)d_in[20]; const float* be2 = (const float*)d_in[21];

    const int M = in_sizes[0] / WIDTH;   // 30000
    const int E = in_sizes[1] / 2;       // 600000

    float *qkvs, *accum, *stats, *biasc;
    __nv_bfloat16 *ahi, *alo, *bthi, *btlo;
    int *deg, *off, *pos, *csr;
    cudaGetSymbolAddress((void**)&qkvs,  g_qkvs);
    cudaGetSymbolAddress((void**)&accum, g_accum);
    cudaGetSymbolAddress((void**)&stats, g_stats);
    cudaGetSymbolAddress((void**)&ahi,   g_ahi);
    cudaGetSymbolAddress((void**)&alo,   g_alo);
    cudaGetSymbolAddress((void**)&bthi,  g_bthi);
    cudaGetSymbolAddress((void**)&btlo,  g_btlo);
    cudaGetSymbolAddress((void**)&biasc, g_biasc);
    cudaGetSymbolAddress((void**)&deg,   g_deg);
    cudaGetSymbolAddress((void**)&off,   g_off);
    cudaGetSymbolAddress((void**)&pos,   g_pos);
    cudaGetSymbolAddress((void**)&csr,   g_csr);

    cudaFuncSetAttribute(gemm_mma, cudaFuncAttributeMaxDynamicSharedMemorySize, SM_BYTES);

    dim3 ggrid(8, (M + 127) / 128);
    int eb = (E + 255) / 256;
    int agg_blocks = (M * 32 + 255) / 256;
    float invN = 1.0f / (float)M;

    // ---- prep (once, single stream) ----
    detect_idx_kernel<<<1, 512>>>((const int*)ei, 2 * E);
    prep_weights<<<dim3(8, 8, 8), dim3(32, 8)>>>(wp, bthi, btlo);
    prep_bias<<<8, 256>>>(wp, biasc);

    // ---- CSR build (once) ----
    cudaMemsetAsync(deg, 0, M * sizeof(int));
    hist_kernel<<<eb, 256>>>(ei, deg, E, M);
    scan_kernel<<<1, 1024>>>(deg, off, pos, M);
    scatter_kernel<<<eb, 256>>>(ei, pos, csr, E, M);

    // ---- layer 1 ----
    split_a_kernel<<<960, 512>>>(x, ahi, alo, M * 64);
    cudaMemsetAsync(stats, 0, 2 * WIDTH * sizeof(float));
    gemm_mma<<<ggrid, 256, SM_BYTES>>>(ahi, alo, bthi, btlo, biasc, qkvs, M);
    edge_agg<<<agg_blocks, 256>>>(qkvs, off, csr, accum, stats, M);
    bn_act_split<<<480, 256>>>(accum, stats, g1, be1, ahi, alo, M * 64, invN);

    // ---- layer 2 ----
    cudaMemsetAsync(stats, 0, 2 * WIDTH * sizeof(float));
    gemm_mma<<<ggrid, 256, SM_BYTES>>>(ahi, alo, bthi + (size_t)1024 * 256,
                                       btlo + (size_t)1024 * 256, biasc + 1024, qkvs, M);
    edge_agg<<<agg_blocks, 256>>>(qkvs, off, csr, accum, stats, M);
    bn_act<<<480, 256>>>(accum, stats, g2, be2, (float*)d_out, M, invN);
}

// round 11
// speedup vs baseline: 1.0998x; 1.0998x over previous
#include <cuda_runtime.h>
#include <cuda_bf16.h>
#include <cstdint>
#include <cstddef>

// Problem constants (fixed by reference)
#define NNODES 30000
#define EMAX   600000
#define WIDTH  256      // heads(4) * per-head(64)
#define QKVS_W 1024     // q|k|v|s concatenated

// ================= scratch (static device globals; no allocation) ===========
__device__ __align__(16) float g_qkvs [(size_t)NNODES * QKVS_W];
__device__ __align__(16) float g_accum[(size_t)NNODES * WIDTH];
__device__ __align__(16) float g_stats[2 * WIDTH];          // sum | sumsq
__device__ int g_is64;

// CSR scratch (built once per launch; reused by both layers)
__device__ int g_deg[NNODES];
__device__ int g_off[NNODES + 1];
__device__ int g_pos[NNODES];
__device__ int g_csr[EMAX];

// bf16 split-precision scratch
__device__ __align__(16) __nv_bfloat16 g_ahi [(size_t)NNODES * 256];
__device__ __align__(16) __nv_bfloat16 g_alo [(size_t)NNODES * 256];
__device__ __align__(16) __nv_bfloat16 g_bthi[2u * 1024 * 256];   // Bt[n][k] per layer
__device__ __align__(16) __nv_bfloat16 g_btlo[2u * 1024 * 256];
__device__ __align__(16) float         g_biasc[2 * 1024];

// ================= small kernels =============================================
__global__ void __launch_bounds__(512) detect_idx_kernel(
    const int* __restrict__ ei32, int nwords) {
    __shared__ int bad;
    if (threadIdx.x == 0) bad = 0;
    __syncthreads();
    int lim = nwords < 4096 ? nwords : 4096;
    int nz = 0;
    for (int i = 1 + 2 * threadIdx.x; i < lim; i += 2 * 512)
        nz |= (ei32[i] != 0);
    if (nz) atomicOr(&bad, 1);
    __syncthreads();
    if (threadIdx.x == 0) g_is64 = !bad;
}

__device__ __forceinline__ int load_idx(const void* ei, int i) {
    if (g_is64) return (int)((const long long*)ei)[i];
    return ((const int*)ei)[i];
}

__global__ void hist_kernel(const void* __restrict__ ei, int* __restrict__ deg,
                            int E, int M) {
    int e = blockIdx.x * blockDim.x + threadIdx.x;
    if (e >= E) return;
    int dst = load_idx(ei, E + e);
    if ((unsigned)dst < (unsigned)M) atomicAdd(&deg[dst], 1);
}

__global__ void __launch_bounds__(1024) scan_kernel(
    const int* __restrict__ deg, int* __restrict__ off, int* __restrict__ pos, int n) {
    __shared__ int s[1024];
    int t = threadIdx.x;
    int chunk = (n + 1023) / 1024;
    int base = t * chunk;
    int sum = 0;
    for (int i = 0; i < chunk; i++) {
        int idx = base + i;
        if (idx < n) sum += deg[idx];
    }
    s[t] = sum;
    __syncthreads();
    for (int d = 1; d < 1024; d <<= 1) {
        int u = (t >= d) ? s[t - d] : 0;
        __syncthreads();
        s[t] += u;
        __syncthreads();
    }
    int run = s[t] - sum;
    for (int i = 0; i < chunk; i++) {
        int idx = base + i;
        if (idx < n) {
            off[idx] = run;
            pos[idx] = run;
            run += deg[idx];
        }
    }
    if (t == 1023) off[n] = s[1023];
}

__global__ void scatter_kernel(const void* __restrict__ ei, int* __restrict__ pos,
                               int* __restrict__ csr, int E, int M) {
    int e = blockIdx.x * blockDim.x + threadIdx.x;
    if (e >= E) return;
    int src = load_idx(ei, e);
    int dst = load_idx(ei, E + e);
    if ((unsigned)dst >= (unsigned)M || (unsigned)src >= (unsigned)M) return;
    int p = atomicAdd(&pos[dst], 1);
    csr[p] = src;
}

// split fp32 -> bf16 hi/lo (4 elems/thread)
__global__ void split_a_kernel(const float* __restrict__ src,
                               __nv_bfloat16* __restrict__ hi,
                               __nv_bfloat16* __restrict__ lo, int n4) {
    int i = blockIdx.x * blockDim.x + threadIdx.x;
    int s = gridDim.x * blockDim.x;
    for (; i < n4; i += s) {
        float4 v = ((const float4*)src)[i];
        __nv_bfloat16 h0 = __float2bfloat16(v.x), h1 = __float2bfloat16(v.y);
        __nv_bfloat16 h2 = __float2bfloat16(v.z), h3 = __float2bfloat16(v.w);
        __nv_bfloat16 l0 = __float2bfloat16(v.x - __bfloat162float(h0));
        __nv_bfloat16 l1 = __float2bfloat16(v.y - __bfloat162float(h1));
        __nv_bfloat16 l2 = __float2bfloat16(v.z - __bfloat162float(h2));
        __nv_bfloat16 l3 = __float2bfloat16(v.w - __bfloat162float(h3));
        ((__nv_bfloat162*)hi)[i * 2]     = __nv_bfloat162(h0, h1);
        ((__nv_bfloat162*)hi)[i * 2 + 1] = __nv_bfloat162(h2, h3);
        ((__nv_bfloat162*)lo)[i * 2]     = __nv_bfloat162(l0, l1);
        ((__nv_bfloat162*)lo)[i * 2 + 1] = __nv_bfloat162(l2, l3);
    }
}

struct WPtrs { const float* w[8]; const float* b[8]; };

__global__ void prep_weights(WPtrs P, __nv_bfloat16* __restrict__ bthi,
                             __nv_bfloat16* __restrict__ btlo) {
    const float* W = P.w[blockIdx.z];
    int layer = blockIdx.z >> 2, j = blockIdx.z & 3;
    __shared__ float t[32][33];
    int tx = threadIdx.x, ty = threadIdx.y;
    int c0 = blockIdx.x * 32, k0 = blockIdx.y * 32;
#pragma unroll
    for (int r = 0; r < 4; r++) {
        int k = k0 + ty + r * 8;
        t[ty + r * 8][tx] = W[k * 256 + c0 + tx];
    }
    __syncthreads();
#pragma unroll
    for (int r = 0; r < 4; r++) {
        int c = c0 + ty + r * 8;
        int k = k0 + tx;
        float v = t[tx][ty + r * 8];
        __nv_bfloat16 h = __float2bfloat16(v);
        size_t o = ((size_t)layer * 1024 + j * 256 + c) * 256 + k;
        bthi[o] = h;
        btlo[o] = __float2bfloat16(v - __bfloat162float(h));
    }
}

__global__ void prep_bias(WPtrs P, float* __restrict__ biasc) {
    int idx = blockIdx.x * blockDim.x + threadIdx.x;
    if (idx < 2048) {
        int layer = idx >> 10, j = (idx >> 8) & 3, c = idx & 255;
        biasc[idx] = P.b[layer * 4 + j][c];
    }
}

// ======== mma.sync bf16 GEMM, 2-stage cp.async, CTA 128x64, 2 CTAs/SM ========
#define KPAD 72
#define A_TILE_B (128 * KPAD)        // bf16 elems per A tile
#define B_TILE_B (64 * KPAD)         // bf16 elems per B tile
#define STAGE_B (2 * A_TILE_B + 2 * B_TILE_B)   // Ah,Al,Bh,Bl
#define SM_BYTES (2 * STAGE_B * 2)   // 110592 bytes -> 2 CTAs/SM

__device__ __forceinline__ void mma16816(float* d, const uint32_t* a,
                                          const uint32_t* b) {
    asm volatile(
        "mma.sync.aligned.m16n8k16.row.col.f32.bf16.bf16.f32 "
        "{%0,%1,%2,%3}, {%4,%5,%6,%7}, {%8,%9}, {%0,%1,%2,%3};"
        : "+f"(d[0]), "+f"(d[1]), "+f"(d[2]), "+f"(d[3])
        : "r"(a[0]), "r"(a[1]), "r"(a[2]), "r"(a[3]), "r"(b[0]), "r"(b[1]));
}

__device__ __forceinline__ void cpa16(uint32_t dst_s, const void* src, bool valid) {
    int sz = valid ? 16 : 0;
    asm volatile("cp.async.cg.shared.global [%0], [%1], 16, %2;"
                 :: "r"(dst_s), "l"(src), "r"(sz));
}

// 128-row tile (A): 4 iterations of 256 threads
__device__ __forceinline__ void load_tile_a(
    uint32_t s, const __nv_bfloat16* __restrict__ g,
    int row0, int rowlim, int k0, int tid) {
#pragma unroll
    for (int it = 0; it < 4; it++) {
        int idx = it * 256 + tid;
        int row = idx >> 3;
        int c8  = (idx & 7) * 8;
        int r = row0 + row;
        cpa16(s + (row * KPAD + c8) * 2, g + (size_t)r * 256 + k0 + c8, r < rowlim);
    }
}

// 64-row tile (B): 2 iterations of 256 threads
__device__ __forceinline__ void load_tile_b(
    uint32_t s, const __nv_bfloat16* __restrict__ g, int k0, int tid) {
#pragma unroll
    for (int it = 0; it < 2; it++) {
        int idx = it * 256 + tid;
        int row = idx >> 3;
        int c8  = (idx & 7) * 8;
        cpa16(s + (row * KPAD + c8) * 2, g + (size_t)row * 256 + k0 + c8, true);
    }
}

__device__ __forceinline__ void issue_stage(
    uint32_t sb, int stage,
    const __nv_bfloat16* ahi, const __nv_bfloat16* alo,
    const __nv_bfloat16* bh, const __nv_bfloat16* bl,
    int m0, int M, int k0, int tid) {
    uint32_t s = sb + stage * STAGE_B * 2;
    load_tile_a(s,                               ahi, m0, M, k0, tid);
    load_tile_a(s + A_TILE_B * 2,                alo, m0, M, k0, tid);
    load_tile_b(s + A_TILE_B * 4,                bh, k0, tid);
    load_tile_b(s + A_TILE_B * 4 + B_TILE_B * 2, bl, k0, tid);
    asm volatile("cp.async.commit_group;");
}

__global__ void __launch_bounds__(256, 2) gemm_mma(
    const __nv_bfloat16* __restrict__ ahi, const __nv_bfloat16* __restrict__ alo,
    const __nv_bfloat16* __restrict__ bthi, const __nv_bfloat16* __restrict__ btlo,
    const float* __restrict__ bias, float* __restrict__ out, int M)
{
    extern __shared__ __align__(16) __nv_bfloat16 sm[];
    uint32_t sb = (uint32_t)__cvta_generic_to_shared(sm);

    const int tid = threadIdx.x;
    const int wid = tid >> 5, lane = tid & 31;
    const int wm = wid & 3, wn = wid >> 2;
    const int g = lane >> 2, t = lane & 3;
    const int nt = blockIdx.x;                 // 0..15 : 64-col block
    const int m0 = blockIdx.y * 128;

    const __nv_bfloat16* bh = bthi + (size_t)nt * 64 * 256;
    const __nv_bfloat16* bl = btlo + (size_t)nt * 64 * 256;

    float acc[2][4][4];
#pragma unroll
    for (int i = 0; i < 2; i++)
#pragma unroll
        for (int j = 0; j < 4; j++)
#pragma unroll
            for (int k = 0; k < 4; k++) acc[i][j][k] = 0.f;

    issue_stage(sb, 0, ahi, alo, bh, bl, m0, M, 0, tid);

    for (int kc = 0; kc < 4; kc++) {
        if (kc + 1 < 4) {
            issue_stage(sb, (kc + 1) & 1, ahi, alo, bh, bl, m0, M, (kc + 1) * 64, tid);
            asm volatile("cp.async.wait_group 1;");
        } else {
            asm volatile("cp.async.wait_group 0;");
        }
        __syncthreads();

        const __nv_bfloat16* sAh = sm + (kc & 1) * STAGE_B;
        const __nv_bfloat16* sAl = sAh + A_TILE_B;
        const __nv_bfloat16* sBh = sAh + 2 * A_TILE_B;
        const __nv_bfloat16* sBl = sBh + B_TILE_B;

#pragma unroll
        for (int ks = 0; ks < 4; ks++) {
            const int kb = ks * 16 + t * 2;
            uint32_t a_h[2][4], a_l[2][4];
#pragma unroll
            for (int mf = 0; mf < 2; mf++) {
                int r = wm * 32 + mf * 16 + g;
                a_h[mf][0] = *(const uint32_t*)(sAh + r * KPAD + kb);
                a_h[mf][1] = *(const uint32_t*)(sAh + (r + 8) * KPAD + kb);
                a_h[mf][2] = *(const uint32_t*)(sAh + r * KPAD + kb + 8);
                a_h[mf][3] = *(const uint32_t*)(sAh + (r + 8) * KPAD + kb + 8);
                a_l[mf][0] = *(const uint32_t*)(sAl + r * KPAD + kb);
                a_l[mf][1] = *(const uint32_t*)(sAl + (r + 8) * KPAD + kb);
                a_l[mf][2] = *(const uint32_t*)(sAl + r * KPAD + kb + 8);
                a_l[mf][3] = *(const uint32_t*)(sAl + (r + 8) * KPAD + kb + 8);
            }
#pragma unroll
            for (int nf = 0; nf < 4; nf++) {
                int c = wn * 32 + nf * 8 + g;
                uint32_t b_h[2], b_l[2];
                b_h[0] = *(const uint32_t*)(sBh + c * KPAD + kb);
                b_h[1] = *(const uint32_t*)(sBh + c * KPAD + kb + 8);
                b_l[0] = *(const uint32_t*)(sBl + c * KPAD + kb);
                b_l[1] = *(const uint32_t*)(sBl + c * KPAD + kb + 8);
#pragma unroll
                for (int mf = 0; mf < 2; mf++) {
                    mma16816(acc[mf][nf], a_h[mf], b_h);
                    mma16816(acc[mf][nf], a_h[mf], b_l);
                    mma16816(acc[mf][nf], a_l[mf], b_h);
                }
            }
        }
        __syncthreads();
    }

#pragma unroll
    for (int mf = 0; mf < 2; mf++) {
        int r0 = m0 + wm * 32 + mf * 16 + g;
#pragma unroll
        for (int nf = 0; nf < 4; nf++) {
            int cg = nt * 64 + wn * 32 + nf * 8 + t * 2;
            float bx = bias[cg], by = bias[cg + 1];
            if (r0 < M) {
                float2 o = make_float2(acc[mf][nf][0] + bx, acc[mf][nf][1] + by);
                *(float2*)(out + (size_t)r0 * QKVS_W + cg) = o;
            }
            if (r0 + 8 < M) {
                float2 o = make_float2(acc[mf][nf][2] + bx, acc[mf][nf][3] + by);
                *(float2*)(out + (size_t)(r0 + 8) * QKVS_W + cg) = o;
            }
        }
    }
}

// ======= gather edge aggregation (2-edge unroll, barrier-free; R8 form) =====
__global__ void __launch_bounds__(256) edge_agg(
    const float* __restrict__ qkvs,
    const int* __restrict__ off, const int* __restrict__ csr,
    float* __restrict__ accum, int M)
{
    int warp = (blockIdx.x * blockDim.x + threadIdx.x) >> 5;
    int lane = threadIdx.x & 31;
    if (warp >= M) return;

    const float4* qp = (const float4*)(qkvs + (size_t)warp * QKVS_W);
    float4 q0 = __ldg(&qp[lane * 2]), q1 = __ldg(&qp[lane * 2 + 1]);

    int i0 = off[warp], i1 = off[warp + 1];
    float a0x = 0.f, a0y = 0.f, a0z = 0.f, a0w = 0.f;
    float a1x = 0.f, a1y = 0.f, a1z = 0.f, a1w = 0.f;
    float dsum = 0.f;

    int i = i0;
    for (; i + 2 <= i1; i += 2) {
        int sa = __ldg(&csr[i]), sb = __ldg(&csr[i + 1]);
        const float4* kpa = (const float4*)(qkvs + (size_t)sa * QKVS_W + 256);
        const float4* vpa = (const float4*)(qkvs + (size_t)sa * QKVS_W + 512);
        const float4* kpb = (const float4*)(qkvs + (size_t)sb * QKVS_W + 256);
        const float4* vpb = (const float4*)(qkvs + (size_t)sb * QKVS_W + 512);
        float4 ka0 = __ldg(&kpa[lane * 2]), ka1 = __ldg(&kpa[lane * 2 + 1]);
        float4 kb0 = __ldg(&kpb[lane * 2]), kb1 = __ldg(&kpb[lane * 2 + 1]);
        float4 va0 = __ldg(&vpa[lane * 2]), va1 = __ldg(&vpa[lane * 2 + 1]);
        float4 vb0 = __ldg(&vpb[lane * 2]), vb1 = __ldg(&vpb[lane * 2 + 1]);

        float pa = q0.x * ka0.x + q0.y * ka0.y + q0.z * ka0.z + q0.w * ka0.w
                 + q1.x * ka1.x + q1.y * ka1.y + q1.z * ka1.z + q1.w * ka1.w;
        float pb = q0.x * kb0.x + q0.y * kb0.y + q0.z * kb0.z + q0.w * kb0.w
                 + q1.x * kb1.x + q1.y * kb1.y + q1.z * kb1.z + q1.w * kb1.w;
        pa += __shfl_xor_sync(0xffffffffu, pa, 1);
        pb += __shfl_xor_sync(0xffffffffu, pb, 1);
        pa += __shfl_xor_sync(0xffffffffu, pa, 2);
        pb += __shfl_xor_sync(0xffffffffu, pb, 2);
        pa += __shfl_xor_sync(0xffffffffu, pa, 4);
        pb += __shfl_xor_sync(0xffffffffu, pb, 4);
        float exa = __expf(pa * 0.125f);
        float exb = __expf(pb * 0.125f);
        dsum += exa + exb;
        a0x += va0.x * exa + vb0.x * exb; a0y += va0.y * exa + vb0.y * exb;
        a0z += va0.z * exa + vb0.z * exb; a0w += va0.w * exa + vb0.w * exb;
        a1x += va1.x * exa + vb1.x * exb; a1y += va1.y * exa + vb1.y * exb;
        a1z += va1.z * exa + vb1.z * exb; a1w += va1.w * exa + vb1.w * exb;
    }
    if (i < i1) {
        int s = __ldg(&csr[i]);
        const float4* kp = (const float4*)(qkvs + (size_t)s * QKVS_W + 256);
        const float4* vp = (const float4*)(qkvs + (size_t)s * QKVS_W + 512);
        float4 k0 = __ldg(&kp[lane * 2]), k1 = __ldg(&kp[lane * 2 + 1]);
        float4 v0 = __ldg(&vp[lane * 2]), v1 = __ldg(&vp[lane * 2 + 1]);
        float p = q0.x * k0.x + q0.y * k0.y + q0.z * k0.z + q0.w * k0.w
                + q1.x * k1.x + q1.y * k1.y + q1.z * k1.z + q1.w * k1.w;
        p += __shfl_xor_sync(0xffffffffu, p, 1);
        p += __shfl_xor_sync(0xffffffffu, p, 2);
        p += __shfl_xor_sync(0xffffffffu, p, 4);
        float ex = __expf(p * 0.125f);
        dsum += ex;
        a0x += v0.x * ex; a0y += v0.y * ex; a0z += v0.z * ex; a0w += v0.w * ex;
        a1x += v1.x * ex; a1y += v1.y * ex; a1z += v1.z * ex; a1w += v1.w * ex;
    }

    float inv = (dsum > 0.f) ? (1.0f / dsum) : 0.f;
    const float4* sp = (const float4*)(qkvs + (size_t)warp * QKVS_W + 768);
    float4 s0 = __ldg(&sp[lane * 2]), s1 = __ldg(&sp[lane * 2 + 1]);
    float4 o0 = make_float4(a0x * inv + s0.x, a0y * inv + s0.y,
                            a0z * inv + s0.z, a0w * inv + s0.w);
    float4 o1 = make_float4(a1x * inv + s1.x, a1y * inv + s1.y,
                            a1z * inv + s1.z, a1w * inv + s1.w);
    float4* op = (float4*)(accum + (size_t)warp * WIDTH + lane * 8);
    op[0] = o0;
    op[1] = o1;
}

// ================= BN stats (separate, R8 form) ==============================
#define FIN_ROWS 32
__global__ void __launch_bounds__(256) stats_kernel(
    const float* __restrict__ accum, float* __restrict__ stats, int M)
{
    const int c = threadIdx.x;
    const int r0 = blockIdx.x * FIN_ROWS;
    float s1 = 0.f, s2 = 0.f;
#pragma unroll 4
    for (int r = 0; r < FIN_ROWS; r++) {
        int n = r0 + r;
        if (n >= M) break;
        float v = accum[(size_t)n * WIDTH + c];
        s1 += v; s2 += v * v;
    }
    atomicAdd(&stats[c], s1);
    atomicAdd(&stats[WIDTH + c], s2);
}

__global__ void __launch_bounds__(256) bn_act(
    const float* __restrict__ in, const float* __restrict__ stats,
    const float* __restrict__ gamma, const float* __restrict__ beta,
    float* __restrict__ out, int M, float invN)
{
    int idx = blockIdx.x * blockDim.x + threadIdx.x;
    int total = M * WIDTH;
    int stride = gridDim.x * blockDim.x;
    for (; idx < total; idx += stride) {
        int c = idx & (WIDTH - 1);
        float mean = stats[c] * invN;
        float var  = stats[WIDTH + c] * invN - mean * mean;
        float sc = rsqrtf(var + 1e-5f) * gamma[c];
        float sh = beta[c] - mean * sc;
        float v = in[idx] * sc + sh;
        out[idx] = (v >= 0.f) ? v : 0.1f * v;
    }
}

// BN + leaky-relu + bf16 hi/lo split, feeding the next GEMM directly
__global__ void __launch_bounds__(256) bn_act_split(
    const float* __restrict__ in, const float* __restrict__ stats,
    const float* __restrict__ gamma, const float* __restrict__ beta,
    __nv_bfloat16* __restrict__ hi, __nv_bfloat16* __restrict__ lo,
    int n4, float invN)
{
    int i = blockIdx.x * blockDim.x + threadIdx.x;
    int stride = gridDim.x * blockDim.x;
    for (; i < n4; i += stride) {
        int c = (i & 63) * 4;
        float4 v = ((const float4*)in)[i];
        float r[4] = {v.x, v.y, v.z, v.w};
        __nv_bfloat16 hh[4], ll[4];
#pragma unroll
        for (int j = 0; j < 4; j++) {
            int cc = c + j;
            float mean = stats[cc] * invN;
            float var  = stats[WIDTH + cc] * invN - mean * mean;
            float sc = rsqrtf(var + 1e-5f) * gamma[cc];
            float sh = beta[cc] - mean * sc;
            float x = r[j] * sc + sh;
            x = (x >= 0.f) ? x : 0.1f * x;
            hh[j] = __float2bfloat16(x);
            ll[j] = __float2bfloat16(x - __bfloat162float(hh[j]));
        }
        ((__nv_bfloat162*)hi)[i * 2]     = __nv_bfloat162(hh[0], hh[1]);
        ((__nv_bfloat162*)hi)[i * 2 + 1] = __nv_bfloat162(hh[2], hh[3]);
        ((__nv_bfloat162*)lo)[i * 2]     = __nv_bfloat162(ll[0], ll[1]);
        ((__nv_bfloat162*)lo)[i * 2 + 1] = __nv_bfloat162(ll[2], ll[3]);
    }
}

// ================= launch ====================================================
extern "C" void kernel_launch(void* const* d_in, const int* in_sizes, int n_in,
                              void* d_out, int out_size)
{
    const float* x  = (const float*)d_in[0];
    const void*  ei = d_in[1];
    WPtrs wp;
    for (int i = 0; i < 4; i++) {
        wp.w[i]     = (const float*)d_in[2 + i * 2];
        wp.b[i]     = (const float*)d_in[3 + i * 2];
        wp.w[4 + i] = (const float*)d_in[12 + i * 2];
        wp.b[4 + i] = (const float*)d_in[13 + i * 2];
    }
    const float* g1  = (const float*)d_in[10]; const float* be1 = (const float*)d_in[11];
    const float* g2  = (const float*)d_in[20]; const float* be2 = (const float*)d_in[21];

    const int M = in_sizes[0] / WIDTH;   // 30000
    const int E = in_sizes[1] / 2;       // 600000

    float *qkvs, *accum, *stats, *biasc;
    __nv_bfloat16 *ahi, *alo, *bthi, *btlo;
    int *deg, *off, *pos, *csr;
    cudaGetSymbolAddress((void**)&qkvs,  g_qkvs);
    cudaGetSymbolAddress((void**)&accum, g_accum);
    cudaGetSymbolAddress((void**)&stats, g_stats);
    cudaGetSymbolAddress((void**)&ahi,   g_ahi);
    cudaGetSymbolAddress((void**)&alo,   g_alo);
    cudaGetSymbolAddress((void**)&bthi,  g_bthi);
    cudaGetSymbolAddress((void**)&btlo,  g_btlo);
    cudaGetSymbolAddress((void**)&biasc, g_biasc);
    cudaGetSymbolAddress((void**)&deg,   g_deg);
    cudaGetSymbolAddress((void**)&off,   g_off);
    cudaGetSymbolAddress((void**)&pos,   g_pos);
    cudaGetSymbolAddress((void**)&csr,   g_csr);

    cudaFuncSetAttribute(gemm_mma, cudaFuncAttributeMaxDynamicSharedMemorySize, SM_BYTES);

    dim3 ggrid(16, (M + 127) / 128);
    int eb = (E + 255) / 256;
    int agg_blocks  = (M * 32 + 255) / 256;
    int stat_blocks = (M + FIN_ROWS - 1) / FIN_ROWS;
    float invN = 1.0f / (float)M;

    // ---- prep (once, single stream) ----
    detect_idx_kernel<<<1, 512>>>((const int*)ei, 2 * E);
    prep_weights<<<dim3(8, 8, 8), dim3(32, 8)>>>(wp, bthi, btlo);
    prep_bias<<<8, 256>>>(wp, biasc);

    // ---- CSR build (once) ----
    cudaMemsetAsync(deg, 0, M * sizeof(int));
    hist_kernel<<<eb, 256>>>(ei, deg, E, M);
    scan_kernel<<<1, 1024>>>(deg, off, pos, M);
    scatter_kernel<<<eb, 256>>>(ei, pos, csr, E, M);

    // ---- layer 1 ----
    split_a_kernel<<<960, 512>>>(x, ahi, alo, M * 64);
    gemm_mma<<<ggrid, 256, SM_BYTES>>>(ahi, alo, bthi, btlo, biasc, qkvs, M);
    edge_agg<<<agg_blocks, 256>>>(qkvs, off, csr, accum, M);
    cudaMemsetAsync(stats, 0, 2 * WIDTH * sizeof(float));
    stats_kernel<<<stat_blocks, 256>>>(accum, stats, M);
    bn_act_split<<<480, 256>>>(accum, stats, g1, be1, ahi, alo, M * 64, invN);

    // ---- layer 2 ----
    gemm_mma<<<ggrid, 256, SM_BYTES>>>(ahi, alo, bthi + (size_t)1024 * 256,
                                       btlo + (size_t)1024 * 256, biasc + 1024, qkvs, M);
    edge_agg<<<agg_blocks, 256>>>(qkvs, off, csr, accum, M);
    cudaMemsetAsync(stats, 0, 2 * WIDTH * sizeof(float));
    stats_kernel<<<stat_blocks, 256>>>(accum, stats, M);
    bn_act<<<480, 256>>>(accum, stats, g2, be2, (float*)d_out, M, invN);
}

// round 12
// speedup vs baseline: 1.1280x; 1.0257x over previous
#include <cuda_runtime.h>
#include <cuda_bf16.h>
#include <cstdint>
#include <cstddef>

// Problem constants (fixed by reference)
#define NNODES 30000
#define EMAX   600000
#define WIDTH  256      // heads(4) * per-head(64)
#define QKVS_W 1024     // q|k|v|s concatenated

// ================= scratch (static device globals; no allocation) ===========
__device__ __align__(16) float g_qkvs [(size_t)NNODES * QKVS_W];
__device__ __align__(16) float g_accum[(size_t)NNODES * WIDTH];
__device__ __align__(16) float g_stats[2 * WIDTH];          // sum | sumsq
__device__ int g_is64;

// CSR scratch (built once per launch; reused by both layers)
__device__ int g_deg[NNODES];
__device__ int g_off[NNODES + 1];
__device__ int g_pos[NNODES];
__device__ int g_csr[EMAX];

// bf16 split-precision scratch
__device__ __align__(16) __nv_bfloat16 g_ahi [(size_t)NNODES * 256];
__device__ __align__(16) __nv_bfloat16 g_alo [(size_t)NNODES * 256];
__device__ __align__(16) __nv_bfloat16 g_bthi[2u * 1024 * 256];   // Bt[n][k] per layer
__device__ __align__(16) __nv_bfloat16 g_btlo[2u * 1024 * 256];
__device__ __align__(16) float         g_biasc[2 * 1024];

// ================= small kernels =============================================
__global__ void __launch_bounds__(512) detect_idx_kernel(
    const int* __restrict__ ei32, int nwords) {
    __shared__ int bad;
    if (threadIdx.x == 0) bad = 0;
    __syncthreads();
    int lim = nwords < 4096 ? nwords : 4096;
    int nz = 0;
    for (int i = 1 + 2 * threadIdx.x; i < lim; i += 2 * 512)
        nz |= (ei32[i] != 0);
    if (nz) atomicOr(&bad, 1);
    __syncthreads();
    if (threadIdx.x == 0) g_is64 = !bad;
}

__device__ __forceinline__ int load_idx(const void* ei, int i) {
    if (g_is64) return (int)((const long long*)ei)[i];
    return ((const int*)ei)[i];
}

__global__ void hist_kernel(const void* __restrict__ ei, int* __restrict__ deg,
                            int E, int M) {
    int e = blockIdx.x * blockDim.x + threadIdx.x;
    if (e >= E) return;
    int dst = load_idx(ei, E + e);
    if ((unsigned)dst < (unsigned)M) atomicAdd(&deg[dst], 1);
}

__global__ void __launch_bounds__(1024) scan_kernel(
    const int* __restrict__ deg, int* __restrict__ off, int* __restrict__ pos, int n) {
    __shared__ int s[1024];
    int t = threadIdx.x;
    int chunk = (n + 1023) / 1024;
    int base = t * chunk;
    int sum = 0;
    for (int i = 0; i < chunk; i++) {
        int idx = base + i;
        if (idx < n) sum += deg[idx];
    }
    s[t] = sum;
    __syncthreads();
    for (int d = 1; d < 1024; d <<= 1) {
        int u = (t >= d) ? s[t - d] : 0;
        __syncthreads();
        s[t] += u;
        __syncthreads();
    }
    int run = s[t] - sum;
    for (int i = 0; i < chunk; i++) {
        int idx = base + i;
        if (idx < n) {
            off[idx] = run;
            pos[idx] = run;
            run += deg[idx];
        }
    }
    if (t == 1023) off[n] = s[1023];
}

__global__ void scatter_kernel(const void* __restrict__ ei, int* __restrict__ pos,
                               int* __restrict__ csr, int E, int M) {
    int e = blockIdx.x * blockDim.x + threadIdx.x;
    if (e >= E) return;
    int src = load_idx(ei, e);
    int dst = load_idx(ei, E + e);
    if ((unsigned)dst >= (unsigned)M || (unsigned)src >= (unsigned)M) return;
    int p = atomicAdd(&pos[dst], 1);
    csr[p] = src;
}

// split fp32 -> bf16 hi/lo (4 elems/thread)
__global__ void split_a_kernel(const float* __restrict__ src,
                               __nv_bfloat16* __restrict__ hi,
                               __nv_bfloat16* __restrict__ lo, int n4) {
    int i = blockIdx.x * blockDim.x + threadIdx.x;
    int s = gridDim.x * blockDim.x;
    for (; i < n4; i += s) {
        float4 v = ((const float4*)src)[i];
        __nv_bfloat16 h0 = __float2bfloat16(v.x), h1 = __float2bfloat16(v.y);
        __nv_bfloat16 h2 = __float2bfloat16(v.z), h3 = __float2bfloat16(v.w);
        __nv_bfloat16 l0 = __float2bfloat16(v.x - __bfloat162float(h0));
        __nv_bfloat16 l1 = __float2bfloat16(v.y - __bfloat162float(h1));
        __nv_bfloat16 l2 = __float2bfloat16(v.z - __bfloat162float(h2));
        __nv_bfloat16 l3 = __float2bfloat16(v.w - __bfloat162float(h3));
        ((__nv_bfloat162*)hi)[i * 2]     = __nv_bfloat162(h0, h1);
        ((__nv_bfloat162*)hi)[i * 2 + 1] = __nv_bfloat162(h2, h3);
        ((__nv_bfloat162*)lo)[i * 2]     = __nv_bfloat162(l0, l1);
        ((__nv_bfloat162*)lo)[i * 2 + 1] = __nv_bfloat162(l2, l3);
    }
}

struct WPtrs { const float* w[8]; const float* b[8]; };

__global__ void prep_weights(WPtrs P, __nv_bfloat16* __restrict__ bthi,
                             __nv_bfloat16* __restrict__ btlo) {
    const float* W = P.w[blockIdx.z];
    int layer = blockIdx.z >> 2, j = blockIdx.z & 3;
    __shared__ float t[32][33];
    int tx = threadIdx.x, ty = threadIdx.y;
    int c0 = blockIdx.x * 32, k0 = blockIdx.y * 32;
#pragma unroll
    for (int r = 0; r < 4; r++) {
        int k = k0 + ty + r * 8;
        t[ty + r * 8][tx] = W[k * 256 + c0 + tx];
    }
    __syncthreads();
#pragma unroll
    for (int r = 0; r < 4; r++) {
        int c = c0 + ty + r * 8;
        int k = k0 + tx;
        float v = t[tx][ty + r * 8];
        __nv_bfloat16 h = __float2bfloat16(v);
        size_t o = ((size_t)layer * 1024 + j * 256 + c) * 256 + k;
        bthi[o] = h;
        btlo[o] = __float2bfloat16(v - __bfloat162float(h));
    }
}

__global__ void prep_bias(WPtrs P, float* __restrict__ biasc) {
    int idx = blockIdx.x * blockDim.x + threadIdx.x;
    if (idx < 2048) {
        int layer = idx >> 10, j = (idx >> 8) & 3, c = idx & 255;
        biasc[idx] = P.b[layer * 4 + j][c];
    }
}

// == mma.sync bf16 GEMM, 2-stage cp.async, CTA 128x64, 4 warps (2x2), 2 CTA/SM =
#define KPAD 72
#define A_TILE_B (128 * KPAD)        // bf16 elems per A tile
#define B_TILE_B (64 * KPAD)         // bf16 elems per B tile
#define STAGE_B (2 * A_TILE_B + 2 * B_TILE_B)   // Ah,Al,Bh,Bl
#define SM_BYTES (2 * STAGE_B * 2)   // 110592 bytes -> 2 CTAs/SM
#define GTHREADS 128

__device__ __forceinline__ void mma16816(float* d, const uint32_t* a,
                                          const uint32_t* b) {
    asm volatile(
        "mma.sync.aligned.m16n8k16.row.col.f32.bf16.bf16.f32 "
        "{%0,%1,%2,%3}, {%4,%5,%6,%7}, {%8,%9}, {%0,%1,%2,%3};"
        : "+f"(d[0]), "+f"(d[1]), "+f"(d[2]), "+f"(d[3])
        : "r"(a[0]), "r"(a[1]), "r"(a[2]), "r"(a[3]), "r"(b[0]), "r"(b[1]));
}

__device__ __forceinline__ void cpa16(uint32_t dst_s, const void* src, bool valid) {
    int sz = valid ? 16 : 0;
    asm volatile("cp.async.cg.shared.global [%0], [%1], 16, %2;"
                 :: "r"(dst_s), "l"(src), "r"(sz));
}

// 128-row tile (A): 8 iterations of 128 threads
__device__ __forceinline__ void load_tile_a(
    uint32_t s, const __nv_bfloat16* __restrict__ g,
    int row0, int rowlim, int k0, int tid) {
#pragma unroll
    for (int it = 0; it < 8; it++) {
        int idx = it * GTHREADS + tid;
        int row = idx >> 3;
        int c8  = (idx & 7) * 8;
        int r = row0 + row;
        cpa16(s + (row * KPAD + c8) * 2, g + (size_t)r * 256 + k0 + c8, r < rowlim);
    }
}

// 64-row tile (B): 4 iterations of 128 threads
__device__ __forceinline__ void load_tile_b(
    uint32_t s, const __nv_bfloat16* __restrict__ g, int k0, int tid) {
#pragma unroll
    for (int it = 0; it < 4; it++) {
        int idx = it * GTHREADS + tid;
        int row = idx >> 3;
        int c8  = (idx & 7) * 8;
        cpa16(s + (row * KPAD + c8) * 2, g + (size_t)row * 256 + k0 + c8, true);
    }
}

__device__ __forceinline__ void issue_stage(
    uint32_t sb, int stage,
    const __nv_bfloat16* ahi, const __nv_bfloat16* alo,
    const __nv_bfloat16* bh, const __nv_bfloat16* bl,
    int m0, int M, int k0, int tid) {
    uint32_t s = sb + stage * STAGE_B * 2;
    load_tile_a(s,                               ahi, m0, M, k0, tid);
    load_tile_a(s + A_TILE_B * 2,                alo, m0, M, k0, tid);
    load_tile_b(s + A_TILE_B * 4,                bh, k0, tid);
    load_tile_b(s + A_TILE_B * 4 + B_TILE_B * 2, bl, k0, tid);
    asm volatile("cp.async.commit_group;");
}

__global__ void __launch_bounds__(GTHREADS, 2) gemm_mma(
    const __nv_bfloat16* __restrict__ ahi, const __nv_bfloat16* __restrict__ alo,
    const __nv_bfloat16* __restrict__ bthi, const __nv_bfloat16* __restrict__ btlo,
    const float* __restrict__ bias, float* __restrict__ out, int M)
{
    extern __shared__ __align__(16) __nv_bfloat16 sm[];
    uint32_t sb = (uint32_t)__cvta_generic_to_shared(sm);

    const int tid = threadIdx.x;
    const int wid = tid >> 5, lane = tid & 31;
    const int wm = wid & 1, wn = wid >> 1;     // 2x2 warp grid
    const int g = lane >> 2, t = lane & 3;
    const int nt = blockIdx.x;                 // 0..15 : 64-col block
    const int m0 = blockIdx.y * 128;

    const __nv_bfloat16* bh = bthi + (size_t)nt * 64 * 256;
    const __nv_bfloat16* bl = btlo + (size_t)nt * 64 * 256;

    float acc[4][4][4];
#pragma unroll
    for (int i = 0; i < 4; i++)
#pragma unroll
        for (int j = 0; j < 4; j++)
#pragma unroll
            for (int k = 0; k < 4; k++) acc[i][j][k] = 0.f;

    issue_stage(sb, 0, ahi, alo, bh, bl, m0, M, 0, tid);

    for (int kc = 0; kc < 4; kc++) {
        if (kc + 1 < 4) {
            issue_stage(sb, (kc + 1) & 1, ahi, alo, bh, bl, m0, M, (kc + 1) * 64, tid);
            asm volatile("cp.async.wait_group 1;");
        } else {
            asm volatile("cp.async.wait_group 0;");
        }
        __syncthreads();

        const __nv_bfloat16* sAh = sm + (kc & 1) * STAGE_B;
        const __nv_bfloat16* sAl = sAh + A_TILE_B;
        const __nv_bfloat16* sBh = sAh + 2 * A_TILE_B;
        const __nv_bfloat16* sBl = sBh + B_TILE_B;

#pragma unroll
        for (int ks = 0; ks < 4; ks++) {
            const int kb = ks * 16 + t * 2;
            uint32_t a_h[4][4], a_l[4][4];
#pragma unroll
            for (int mf = 0; mf < 4; mf++) {
                int r = wm * 64 + mf * 16 + g;
                a_h[mf][0] = *(const uint32_t*)(sAh + r * KPAD + kb);
                a_h[mf][1] = *(const uint32_t*)(sAh + (r + 8) * KPAD + kb);
                a_h[mf][2] = *(const uint32_t*)(sAh + r * KPAD + kb + 8);
                a_h[mf][3] = *(const uint32_t*)(sAh + (r + 8) * KPAD + kb + 8);
                a_l[mf][0] = *(const uint32_t*)(sAl + r * KPAD + kb);
                a_l[mf][1] = *(const uint32_t*)(sAl + (r + 8) * KPAD + kb);
                a_l[mf][2] = *(const uint32_t*)(sAl + r * KPAD + kb + 8);
                a_l[mf][3] = *(const uint32_t*)(sAl + (r + 8) * KPAD + kb + 8);
            }
#pragma unroll
            for (int nf = 0; nf < 4; nf++) {
                int c = wn * 32 + nf * 8 + g;
                uint32_t b_h[2], b_l[2];
                b_h[0] = *(const uint32_t*)(sBh + c * KPAD + kb);
                b_h[1] = *(const uint32_t*)(sBh + c * KPAD + kb + 8);
                b_l[0] = *(const uint32_t*)(sBl + c * KPAD + kb);
                b_l[1] = *(const uint32_t*)(sBl + c * KPAD + kb + 8);
#pragma unroll
                for (int mf = 0; mf < 4; mf++) {
                    mma16816(acc[mf][nf], a_h[mf], b_h);
                    mma16816(acc[mf][nf], a_h[mf], b_l);
                    mma16816(acc[mf][nf], a_l[mf], b_h);
                }
            }
        }
        __syncthreads();
    }

#pragma unroll
    for (int mf = 0; mf < 4; mf++) {
        int r0 = m0 + wm * 64 + mf * 16 + g;
#pragma unroll
        for (int nf = 0; nf < 4; nf++) {
            int cg = nt * 64 + wn * 32 + nf * 8 + t * 2;
            float bx = bias[cg], by = bias[cg + 1];
            if (r0 < M) {
                float2 o = make_float2(acc[mf][nf][0] + bx, acc[mf][nf][1] + by);
                *(float2*)(out + (size_t)r0 * QKVS_W + cg) = o;
            }
            if (r0 + 8 < M) {
                float2 o = make_float2(acc[mf][nf][2] + bx, acc[mf][nf][3] + by);
                *(float2*)(out + (size_t)(r0 + 8) * QKVS_W + cg) = o;
            }
        }
    }
}

// ======= gather edge aggregation (2-edge unroll, barrier-free) ==============
__global__ void __launch_bounds__(256) edge_agg(
    const float* __restrict__ qkvs,
    const int* __restrict__ off, const int* __restrict__ csr,
    float* __restrict__ accum, int M)
{
    int warp = (blockIdx.x * blockDim.x + threadIdx.x) >> 5;
    int lane = threadIdx.x & 31;
    if (warp >= M) return;

    const float4* qp = (const float4*)(qkvs + (size_t)warp * QKVS_W);
    float4 q0 = __ldg(&qp[lane * 2]), q1 = __ldg(&qp[lane * 2 + 1]);

    int i0 = off[warp], i1 = off[warp + 1];
    float a0x = 0.f, a0y = 0.f, a0z = 0.f, a0w = 0.f;
    float a1x = 0.f, a1y = 0.f, a1z = 0.f, a1w = 0.f;
    float dsum = 0.f;

    int i = i0;
    for (; i + 2 <= i1; i += 2) {
        int sa = __ldg(&csr[i]), sb = __ldg(&csr[i + 1]);
        const float4* kpa = (const float4*)(qkvs + (size_t)sa * QKVS_W + 256);
        const float4* vpa = (const float4*)(qkvs + (size_t)sa * QKVS_W + 512);
        const float4* kpb = (const float4*)(qkvs + (size_t)sb * QKVS_W + 256);
        const float4* vpb = (const float4*)(qkvs + (size_t)sb * QKVS_W + 512);
        float4 ka0 = __ldg(&kpa[lane * 2]), ka1 = __ldg(&kpa[lane * 2 + 1]);
        float4 kb0 = __ldg(&kpb[lane * 2]), kb1 = __ldg(&kpb[lane * 2 + 1]);
        float4 va0 = __ldg(&vpa[lane * 2]), va1 = __ldg(&vpa[lane * 2 + 1]);
        float4 vb0 = __ldg(&vpb[lane * 2]), vb1 = __ldg(&vpb[lane * 2 + 1]);

        float pa = q0.x * ka0.x + q0.y * ka0.y + q0.z * ka0.z + q0.w * ka0.w
                 + q1.x * ka1.x + q1.y * ka1.y + q1.z * ka1.z + q1.w * ka1.w;
        float pb = q0.x * kb0.x + q0.y * kb0.y + q0.z * kb0.z + q0.w * kb0.w
                 + q1.x * kb1.x + q1.y * kb1.y + q1.z * kb1.z + q1.w * kb1.w;
        pa += __shfl_xor_sync(0xffffffffu, pa, 1);
        pb += __shfl_xor_sync(0xffffffffu, pb, 1);
        pa += __shfl_xor_sync(0xffffffffu, pa, 2);
        pb += __shfl_xor_sync(0xffffffffu, pb, 2);
        pa += __shfl_xor_sync(0xffffffffu, pa, 4);
        pb += __shfl_xor_sync(0xffffffffu, pb, 4);
        float exa = __expf(pa * 0.125f);
        float exb = __expf(pb * 0.125f);
        dsum += exa + exb;
        a0x += va0.x * exa + vb0.x * exb; a0y += va0.y * exa + vb0.y * exb;
        a0z += va0.z * exa + vb0.z * exb; a0w += va0.w * exa + vb0.w * exb;
        a1x += va1.x * exa + vb1.x * exb; a1y += va1.y * exa + vb1.y * exb;
        a1z += va1.z * exa + vb1.z * exb; a1w += va1.w * exa + vb1.w * exb;
    }
    if (i < i1) {
        int s = __ldg(&csr[i]);
        const float4* kp = (const float4*)(qkvs + (size_t)s * QKVS_W + 256);
        const float4* vp = (const float4*)(qkvs + (size_t)s * QKVS_W + 512);
        float4 k0 = __ldg(&kp[lane * 2]), k1 = __ldg(&kp[lane * 2 + 1]);
        float4 v0 = __ldg(&vp[lane * 2]), v1 = __ldg(&vp[lane * 2 + 1]);
        float p = q0.x * k0.x + q0.y * k0.y + q0.z * k0.z + q0.w * k0.w
                + q1.x * k1.x + q1.y * k1.y + q1.z * k1.z + q1.w * k1.w;
        p += __shfl_xor_sync(0xffffffffu, p, 1);
        p += __shfl_xor_sync(0xffffffffu, p, 2);
        p += __shfl_xor_sync(0xffffffffu, p, 4);
        float ex = __expf(p * 0.125f);
        dsum += ex;
        a0x += v0.x * ex; a0y += v0.y * ex; a0z += v0.z * ex; a0w += v0.w * ex;
        a1x += v1.x * ex; a1y += v1.y * ex; a1z += v1.z * ex; a1w += v1.w * ex;
    }

    float inv = (dsum > 0.f) ? (1.0f / dsum) : 0.f;
    const float4* sp = (const float4*)(qkvs + (size_t)warp * QKVS_W + 768);
    float4 s0 = __ldg(&sp[lane * 2]), s1 = __ldg(&sp[lane * 2 + 1]);
    float4 o0 = make_float4(a0x * inv + s0.x, a0y * inv + s0.y,
                            a0z * inv + s0.z, a0w * inv + s0.w);
    float4 o1 = make_float4(a1x * inv + s1.x, a1y * inv + s1.y,
                            a1z * inv + s1.z, a1w * inv + s1.w);
    float4* op = (float4*)(accum + (size_t)warp * WIDTH + lane * 8);
    op[0] = o0;
    op[1] = o1;
}

// ================= BN stats ==================================================
#define FIN_ROWS 32
__global__ void __launch_bounds__(256) stats_kernel(
    const float* __restrict__ accum, float* __restrict__ stats, int M)
{
    const int c = threadIdx.x;
    const int r0 = blockIdx.x * FIN_ROWS;
    float s1 = 0.f, s2 = 0.f;
#pragma unroll 4
    for (int r = 0; r < FIN_ROWS; r++) {
        int n = r0 + r;
        if (n >= M) break;
        float v = accum[(size_t)n * WIDTH + c];
        s1 += v; s2 += v * v;
    }
    atomicAdd(&stats[c], s1);
    atomicAdd(&stats[WIDTH + c], s2);
}

__global__ void __launch_bounds__(256) bn_act(
    const float* __restrict__ in, const float* __restrict__ stats,
    const float* __restrict__ gamma, const float* __restrict__ beta,
    float* __restrict__ out, int M, float invN)
{
    int idx = blockIdx.x * blockDim.x + threadIdx.x;
    int total = M * WIDTH;
    int stride = gridDim.x * blockDim.x;
    for (; idx < total; idx += stride) {
        int c = idx & (WIDTH - 1);
        float mean = stats[c] * invN;
        float var  = stats[WIDTH + c] * invN - mean * mean;
        float sc = rsqrtf(var + 1e-5f) * gamma[c];
        float sh = beta[c] - mean * sc;
        float v = in[idx] * sc + sh;
        out[idx] = (v >= 0.f) ? v : 0.1f * v;
    }
}

// BN + leaky-relu + bf16 hi/lo split, feeding the next GEMM directly
__global__ void __launch_bounds__(256) bn_act_split(
    const float* __restrict__ in, const float* __restrict__ stats,
    const float* __restrict__ gamma, const float* __restrict__ beta,
    __nv_bfloat16* __restrict__ hi, __nv_bfloat16* __restrict__ lo,
    int n4, float invN)
{
    int i = blockIdx.x * blockDim.x + threadIdx.x;
    int stride = gridDim.x * blockDim.x;
    for (; i < n4; i += stride) {
        int c = (i & 63) * 4;
        float4 v = ((const float4*)in)[i];
        float r[4] = {v.x, v.y, v.z, v.w};
        __nv_bfloat16 hh[4], ll[4];
#pragma unroll
        for (int j = 0; j < 4; j++) {
            int cc = c + j;
            float mean = stats[cc] * invN;
            float var  = stats[WIDTH + cc] * invN - mean * mean;
            float sc = rsqrtf(var + 1e-5f) * gamma[cc];
            float sh = beta[cc] - mean * sc;
            float x = r[j] * sc + sh;
            x = (x >= 0.f) ? x : 0.1f * x;
            hh[j] = __float2bfloat16(x);
            ll[j] = __float2bfloat16(x - __bfloat162float(hh[j]));
        }
        ((__nv_bfloat162*)hi)[i * 2]     = __nv_bfloat162(hh[0], hh[1]);
        ((__nv_bfloat162*)hi)[i * 2 + 1] = __nv_bfloat162(hh[2], hh[3]);
        ((__nv_bfloat162*)lo)[i * 2]     = __nv_bfloat162(ll[0], ll[1]);
        ((__nv_bfloat162*)lo)[i * 2 + 1] = __nv_bfloat162(ll[2], ll[3]);
    }
}

// ================= launch ====================================================
extern "C" void kernel_launch(void* const* d_in, const int* in_sizes, int n_in,
                              void* d_out, int out_size)
{
    const float* x  = (const float*)d_in[0];
    const void*  ei = d_in[1];
    WPtrs wp;
    for (int i = 0; i < 4; i++) {
        wp.w[i]     = (const float*)d_in[2 + i * 2];
        wp.b[i]     = (const float*)d_in[3 + i * 2];
        wp.w[4 + i] = (const float*)d_in[12 + i * 2];
        wp.b[4 + i] = (const float*)d_in[13 + i * 2];
    }
    const float* g1  = (const float*)d_in[10]; const float* be1 = (const float*)d_in[11];
    const float* g2  = (const float*)d_in[20]; const float* be2 = (const float*)d_in[21];

    const int M = in_sizes[0] / WIDTH;   // 30000
    const int E = in_sizes[1] / 2;       // 600000

    float *qkvs, *accum, *stats, *biasc;
    __nv_bfloat16 *ahi, *alo, *bthi, *btlo;
    int *deg, *off, *pos, *csr;
    cudaGetSymbolAddress((void**)&qkvs,  g_qkvs);
    cudaGetSymbolAddress((void**)&accum, g_accum);
    cudaGetSymbolAddress((void**)&stats, g_stats);
    cudaGetSymbolAddress((void**)&ahi,   g_ahi);
    cudaGetSymbolAddress((void**)&alo,   g_alo);
    cudaGetSymbolAddress((void**)&bthi,  g_bthi);
    cudaGetSymbolAddress((void**)&btlo,  g_btlo);
    cudaGetSymbolAddress((void**)&biasc, g_biasc);
    cudaGetSymbolAddress((void**)&deg,   g_deg);
    cudaGetSymbolAddress((void**)&off,   g_off);
    cudaGetSymbolAddress((void**)&pos,   g_pos);
    cudaGetSymbolAddress((void**)&csr,   g_csr);

    cudaFuncSetAttribute(gemm_mma, cudaFuncAttributeMaxDynamicSharedMemorySize, SM_BYTES);

    dim3 ggrid(16, (M + 127) / 128);
    int eb = (E + 255) / 256;
    int agg_blocks  = (M * 32 + 255) / 256;
    int stat_blocks = (M + FIN_ROWS - 1) / FIN_ROWS;
    float invN = 1.0f / (float)M;

    // ---- prep (once, single stream) ----
    detect_idx_kernel<<<1, 512>>>((const int*)ei, 2 * E);
    prep_weights<<<dim3(8, 8, 8), dim3(32, 8)>>>(wp, bthi, btlo);
    prep_bias<<<8, 256>>>(wp, biasc);

    // ---- CSR build (once) ----
    cudaMemsetAsync(deg, 0, M * sizeof(int));
    hist_kernel<<<eb, 256>>>(ei, deg, E, M);
    scan_kernel<<<1, 1024>>>(deg, off, pos, M);
    scatter_kernel<<<eb, 256>>>(ei, pos, csr, E, M);

    // ---- layer 1 ----
    split_a_kernel<<<960, 512>>>(x, ahi, alo, M * 64);
    gemm_mma<<<ggrid, GTHREADS, SM_BYTES>>>(ahi, alo, bthi, btlo, biasc, qkvs, M);
    edge_agg<<<agg_blocks, 256>>>(qkvs, off, csr, accum, M);
    cudaMemsetAsync(stats, 0, 2 * WIDTH * sizeof(float));
    stats_kernel<<<stat_blocks, 256>>>(accum, stats, M);
    bn_act_split<<<480, 256>>>(accum, stats, g1, be1, ahi, alo, M * 64, invN);

    // ---- layer 2 ----
    gemm_mma<<<ggrid, GTHREADS, SM_BYTES>>>(ahi, alo, bthi + (size_t)1024 * 256,
                                            btlo + (size_t)1024 * 256, biasc + 1024, qkvs, M);
    edge_agg<<<agg_blocks, 256>>>(qkvs, off, csr, accum, M);
    cudaMemsetAsync(stats, 0, 2 * WIDTH * sizeof(float));
    stats_kernel<<<stat_blocks, 256>>>(accum, stats, M);
    bn_act<<<480, 256>>>(accum, stats, g2, be2, (float*)d_out, M, invN);
}